// round 6
// baseline (speedup 1.0000x reference)
#include <cuda_runtime.h>
#include <cstdint>

#define B_    32
#define HW_   128
#define NPIX  16384
#define NIMG  2048
#define PMGRID 296   // 2 blocks per SM on 148-SM GB300

// 128MB scratch: f2 (tf32-rounded) transposed [b,c,w,h], then (f6+f2) in-place
__device__ float g_scratch[(size_t)B_ * 64 * NPIX];
// pre-converted tf32 weights in per-thread fragment order
__device__ float g_wtf[8192];

// XOR-swizzled smem layout for fwht, stride 128 words (no pad)
__device__ __forceinline__ int sidx(int r, int h) {
    return r * 128 + ((((h >> 2) ^ r) & 31) << 2) + (h & 3);
}
__device__ __forceinline__ int sidx4(int r, int h4) {
    return r * 128 + (((h4 ^ r) & 31) << 2);
}

__device__ __forceinline__ uint32_t f2tf(float x) {
    uint32_t r; asm("cvt.rna.tf32.f32 %0, %1;" : "=r"(r) : "f"(x)); return r;
}
__device__ __forceinline__ float softth(float x, float t) {
    float tt = fmaxf(t, 0.f);
    return copysignf(fmaxf(fabsf(x) - tt, 0.f), x);
}
__device__ __forceinline__ void mma_tf32(float* d, uint32_t a0, uint32_t a1, uint32_t a2, uint32_t a3,
                                         uint32_t b0, uint32_t b1) {
    asm volatile(
        "mma.sync.aligned.m16n8k8.row.col.f32.tf32.tf32.f32 "
        "{%0,%1,%2,%3}, {%4,%5,%6,%7}, {%8,%9}, {%0,%1,%2,%3};\n"
        : "+f"(d[0]), "+f"(d[1]), "+f"(d[2]), "+f"(d[3])
        : "r"(a0), "r"(a1), "r"(a2), "r"(a3), "r"(b0), "r"(b1));
}

// packed f32x2 helpers
__device__ __forceinline__ unsigned long long pk2(float x, float y) {
    unsigned long long r;
    asm("mov.b64 %0, {%1,%2};" : "=l"(r) : "f"(x), "f"(y));
    return r;
}
__device__ __forceinline__ float2 upk2(unsigned long long v) {
    float2 f;
    asm("mov.b64 {%0,%1}, %2;" : "=f"(f.x), "=f"(f.y) : "l"(v));
    return f;
}
__device__ __forceinline__ unsigned long long add2(unsigned long long a, unsigned long long b) {
    unsigned long long r;
    asm("add.rn.f32x2 %0, %1, %2;" : "=l"(r) : "l"(a), "l"(b));
    return r;
}
__device__ __forceinline__ unsigned long long sub2(unsigned long long a, unsigned long long b) {
    unsigned long long r;
    const unsigned long long NEG1 = 0xBF800000BF800000ULL;   // (-1.f, -1.f)
    asm("fma.rn.f32x2 %0, %1, %2, %3;" : "=l"(r) : "l"(b), "l"(NEG1), "l"(a));
    return r;
}

// cp.async helpers
__device__ __forceinline__ void cpa16(uint32_t d, const void* s) {
    asm volatile("cp.async.cg.shared.global [%0], [%1], 16;" :: "r"(d), "l"(s));
}
__device__ __forceinline__ void cpa4(uint32_t d, const void* s) {
    asm volatile("cp.async.ca.shared.global [%0], [%1], 4;" :: "r"(d), "l"(s));
}

// ---------------------------------------------------------------------------
// prep: conv_w -> tf32, fragment-ordered for podmix mainloop
// ---------------------------------------------------------------------------
__global__ void prep_kernel(const float* __restrict__ W)
{
    int t = blockIdx.x * 256 + threadIdx.x;
    if (t >= 1024) return;
    int tig = t & 3, gid = (t >> 2) & 7, mq = (t >> 5) & 3, kb = t >> 7;
    int k0 = kb * 8 + tig;
    int r0 = mq * 16 + gid;
    float* o = g_wtf + t * 8;
    o[0] = __uint_as_float(f2tf(__ldg(W + r0 * 64 + k0)));
    o[1] = __uint_as_float(f2tf(__ldg(W + (r0 + 8) * 64 + k0)));
    o[2] = __uint_as_float(f2tf(__ldg(W + r0 * 64 + k0 + 4)));
    o[3] = __uint_as_float(f2tf(__ldg(W + (r0 + 8) * 64 + k0 + 4)));
    int r1 = r0 + 64;
    o[4] = __uint_as_float(f2tf(__ldg(W + r1 * 64 + k0)));
    o[5] = __uint_as_float(f2tf(__ldg(W + (r1 + 8) * 64 + k0)));
    o[6] = __uint_as_float(f2tf(__ldg(W + r1 * 64 + k0 + 4)));
    o[7] = __uint_as_float(f2tf(__ldg(W + (r1 + 8) * 64 + k0 + 4)));
}

// ---------------------------------------------------------------------------
// Pass 1 / Pass 3: 2D FWHT of 128x128 image, output TRANSPOSED, scaled.
// Butterflies packed as f32x2. Stage order: 64 (at fold), 1, 2..32 per axis.
// ---------------------------------------------------------------------------
__global__ void __launch_bounds__(256, 2)
fwht2d_kernel(const float* __restrict__ in, float* __restrict__ out,
              float scale, int do_round)
{
    extern __shared__ float s[];
    const int img = blockIdx.x;
    const int tid = threadIdx.x;
    const float* gin  = in  + (size_t)img * NPIX;
    float*       gout = out + (size_t)img * NPIX;

    #pragma unroll
    for (int k = 0; k < 16; k++) {
        int gi = k * 256 + tid;
        int r  = gi >> 5;
        int c4 = gi & 31;
        float4 v4 = __ldg((const float4*)gin + gi);
        *(float4*)&s[sidx4(r, c4)] = v4;
    }
    __syncthreads();

    unsigned long long q[32];

    // phase W: transform along last axis. thread = (row r, half)
    {
        int r = tid >> 1, half = tid & 1;
        #pragma unroll
        for (int j4 = 0; j4 < 16; j4++) {
            float4 a = *(const float4*)&s[sidx4(r, j4)];
            float4 b = *(const float4*)&s[sidx4(r, j4 + 16)];
            float t0, t1, t2, t3;
            if (half) { t0 = a.x-b.x; t1 = a.y-b.y; t2 = a.z-b.z; t3 = a.w-b.w; }
            else      { t0 = a.x+b.x; t1 = a.y+b.y; t2 = a.z+b.z; t3 = a.w+b.w; }
            q[2*j4]   = pk2(t0 + t1, t0 - t1);
            q[2*j4+1] = pk2(t2 + t3, t2 - t3);
        }
        #pragma unroll
        for (int stp = 1; stp < 32; stp <<= 1)
            #pragma unroll
            for (int p = 0; p < 32; p++)
                if ((p & stp) == 0) {
                    unsigned long long A = q[p], Bv = q[p + stp];
                    q[p] = add2(A, Bv);  q[p + stp] = sub2(A, Bv);
                }
        __syncthreads();
        #pragma unroll
        for (int j4 = 0; j4 < 16; j4++) {
            float2 lo = upk2(q[2*j4]), hi = upk2(q[2*j4+1]);
            *(float4*)&s[sidx4(r, half * 16 + j4)] = make_float4(lo.x, lo.y, hi.x, hi.y);
        }
    }
    __syncthreads();

    // phase H: transform along first axis. thread = (col w, half hh); writes transposed
    {
        int w = tid & 127, hh = tid >> 7;
        #pragma unroll
        for (int p = 0; p < 32; p++) {
            float a0 = s[sidx(2*p,     w)], b0 = s[sidx(2*p + 64, w)];
            float a1 = s[sidx(2*p + 1, w)], b1 = s[sidx(2*p + 65, w)];
            float t0 = hh ? (a0 - b0) : (a0 + b0);
            float t1 = hh ? (a1 - b1) : (a1 + b1);
            q[p] = pk2(t0 + t1, t0 - t1);
        }
        #pragma unroll
        for (int stp = 1; stp < 32; stp <<= 1)
            #pragma unroll
            for (int p = 0; p < 32; p++)
                if ((p & stp) == 0) {
                    unsigned long long A = q[p], Bv = q[p + stp];
                    q[p] = add2(A, Bv);  q[p + stp] = sub2(A, Bv);
                }
        __syncthreads();
        #pragma unroll
        for (int j4 = 0; j4 < 16; j4++) {
            float2 lo = upk2(q[2*j4]), hi = upk2(q[2*j4+1]);
            *(float4*)&s[sidx4(w, hh * 16 + j4)] = make_float4(lo.x, lo.y, hi.x, hi.y);
        }
    }
    __syncthreads();

    if (do_round) {
        #pragma unroll
        for (int k = 0; k < 16; k++) {
            int gi = k * 256 + tid;
            int r  = gi >> 5;
            int c4 = gi & 31;
            float4 t = *(const float4*)&s[sidx4(r, c4)];
            ((float4*)gout)[gi] = make_float4(
                __uint_as_float(f2tf(t.x)), __uint_as_float(f2tf(t.y)),
                __uint_as_float(f2tf(t.z)), __uint_as_float(f2tf(t.w)));
        }
    } else {
        #pragma unroll
        for (int k = 0; k < 16; k++) {
            int gi = k * 256 + tid;
            int r  = gi >> 5;
            int c4 = gi & 31;
            float4 t = *(const float4*)&s[sidx4(r, c4)];
            ((float4*)gout)[gi] = make_float4(t.x*scale, t.y*scale, t.z*scale, t.w*scale);
        }
    }
}

// ---------------------------------------------------------------------------
// Pass 2: persistent double-buffered podmix. Each block loops over tiles
// t = bid + 296*i, prefetching tile t+296 via cp.async while computing t.
// smem: Bs[2][64][136] (tf32 f2 tile) + vt[2][4][128]  = 73728 B
// ---------------------------------------------------------------------------
__global__ void __launch_bounds__(256, 2)
podmix_kernel(float* __restrict__ f2, const float* __restrict__ v,
              const float* __restrict__ T)
{
    extern __shared__ float sm[];
    const int tid  = threadIdx.x;
    const int wid  = tid >> 5;
    const int lane = tid & 31;
    const int gid  = lane >> 2;
    const int tig  = lane & 3;
    const int mq   = wid & 3;
    const int nh   = wid >> 2;
    const int bid  = blockIdx.x;

    auto prefetch = [&](int t, int buf) {
        int b = t >> 7, w = t & 127;
        const float* gt = f2 + (((size_t)b * 64) * 128 + w) * 128;
        uint32_t bsd = (uint32_t)__cvta_generic_to_shared(sm + buf * 8704);
        #pragma unroll
        for (int k = 0; k < 8; k++) {
            int i4 = k * 256 + tid, c = i4 >> 5, h4 = i4 & 31;
            cpa16(bsd + (c * 136 + h4 * 4) * 4, gt + (size_t)c * NPIX + h4 * 4);
        }
        uint32_t vtd = (uint32_t)__cvta_generic_to_shared(sm + 17408 + buf * 512);
        if (tid < 128) {
            cpa4(vtd + tid * 4,        v + tid * 128 + w);
            cpa4(vtd + 512 + tid * 4,  T + tid * 128 + w);
        } else {
            int h = tid - 128;
            cpa4(vtd + 1024 + h * 4, v + NPIX + h * 128 + w);
            cpa4(vtd + 1536 + h * 4, T + NPIX + h * 128 + w);
        }
        asm volatile("cp.async.commit_group;" ::: "memory");
    };

    prefetch(bid, 0);

    const float4* Aw = (const float4*)g_wtf;

    for (int t = bid, it = 0; t < 4096; t += PMGRID, ++it) {
        const int buf = it & 1;
        const int tn  = t + PMGRID;
        if (tn < 4096) {
            prefetch(tn, buf ^ 1);
            asm volatile("cp.async.wait_group 1;" ::: "memory");
        } else {
            asm volatile("cp.async.wait_group 0;" ::: "memory");
        }
        __syncthreads();

        float*    Bs  = sm + buf * 8704;
        uint32_t* Bsu = (uint32_t*)Bs;
        const float* vs0 = sm + 17408 + buf * 512;
        const float* Ts0 = vs0 + 128;
        const float* vs1 = vs0 + 256;
        const float* Ts1 = vs0 + 384;
        const int b = t >> 7, w = t & 127;
        float* gt = f2 + (((size_t)b * 64) * 128 + w) * 128;

        float acc[16][4];
        #pragma unroll
        for (int i = 0; i < 16; i++) {
            acc[i][0] = 0.f; acc[i][1] = 0.f; acc[i][2] = 0.f; acc[i][3] = 0.f;
        }

        #pragma unroll
        for (int kb = 0; kb < 8; kb++) {
            int ai = (((kb * 4 + mq) * 8 + gid) * 4 + tig) * 2;
            float4 lo = __ldg(Aw + ai);
            float4 hi = __ldg(Aw + ai + 1);
            uint32_t a0 = __float_as_uint(lo.x), a1 = __float_as_uint(lo.y);
            uint32_t a2 = __float_as_uint(lo.z), a3 = __float_as_uint(lo.w);
            uint32_t a4 = __float_as_uint(hi.x), a5 = __float_as_uint(hi.y);
            uint32_t a6 = __float_as_uint(hi.z), a7 = __float_as_uint(hi.w);
            int r0 = (kb * 8 + tig) * 136 + nh * 64 + gid;
            int r1 = r0 + 4 * 136;
            #pragma unroll
            for (int nb = 0; nb < 8; nb++) {
                uint32_t b0 = Bsu[r0 + nb * 8];
                uint32_t b1 = Bsu[r1 + nb * 8];
                mma_tf32(acc[nb],     a0, a1, a2, a3, b0, b1);   // pod 0
                mma_tf32(acc[8 + nb], a4, a5, a6, a7, b0, b1);   // pod 1
            }
        }
        __syncthreads();   // all GEMM reads of Bs done

        // epilogue: combine pods in registers, add f2, write back into Bs
        {
            const int o = mq * 16 + gid;
            #pragma unroll
            for (int nb = 0; nb < 8; nb++) {
                int h = nh * 64 + nb * 8 + 2 * tig;
                float v0h = vs0[h], v0h1 = vs0[h+1], t0h = Ts0[h], t0h1 = Ts0[h+1];
                float v1h = vs1[h], v1h1 = vs1[h+1], t1h = Ts1[h], t1h1 = Ts1[h+1];
                float2 f0 = *(const float2*)&Bs[o * 136 + h];
                float2 f1 = *(const float2*)&Bs[(o + 8) * 136 + h];
                float2 r0 = make_float2(
                    softth(v0h  * acc[nb][0], t0h)  + softth(v1h  * acc[8+nb][0], t1h)  + f0.x,
                    softth(v0h1 * acc[nb][1], t0h1) + softth(v1h1 * acc[8+nb][1], t1h1) + f0.y);
                float2 r1 = make_float2(
                    softth(v0h  * acc[nb][2], t0h)  + softth(v1h  * acc[8+nb][2], t1h)  + f1.x,
                    softth(v0h1 * acc[nb][3], t0h1) + softth(v1h1 * acc[8+nb][3], t1h1) + f1.y);
                *(float2*)&Bs[o * 136 + h]       = r0;
                *(float2*)&Bs[(o + 8) * 136 + h] = r1;
            }
        }
        __syncthreads();   // epilogue writes + vt reads done

        // coalesced store; each thread reads exactly the cells its next-iter
        // prefetch will overwrite (identical index mapping -> per-thread order)
        #pragma unroll
        for (int k = 0; k < 8; k++) {
            int i4 = k * 256 + tid;
            int c  = i4 >> 5;
            int h4 = i4 & 31;
            float4 tv = *(const float4*)&Bs[c * 136 + h4 * 4];
            *((float4*)(gt + (size_t)c * NPIX) + h4) = tv;
        }
    }
}

extern "C" void kernel_launch(void* const* d_in, const int* in_sizes, int n_in,
                              void* d_out, int out_size)
{
    (void)in_sizes; (void)n_in; (void)out_size;
    const float* x = (const float*)d_in[0];
    const float* v = (const float*)d_in[1];
    const float* T = (const float*)d_in[2];
    const float* W = (const float*)d_in[3];
    float* out = (float*)d_out;

    float* scratch = nullptr;
    cudaGetSymbolAddress((void**)&scratch, g_scratch);

    const int smem1 = 128 * 128 * 4;          // 65536 B
    const int smem2 = (17408 + 1024) * 4;     // 73728 B
    cudaFuncSetAttribute(fwht2d_kernel, cudaFuncAttributeMaxDynamicSharedMemorySize, smem1);
    cudaFuncSetAttribute(podmix_kernel, cudaFuncAttributeMaxDynamicSharedMemorySize, smem2);

    prep_kernel<<<4, 256>>>(W);
    fwht2d_kernel<<<NIMG, 256, smem1>>>(x, scratch, 1.0f, 1);
    podmix_kernel<<<PMGRID, 256, smem2>>>(scratch, v, T);
    fwht2d_kernel<<<NIMG, 256, smem1>>>(scratch, out, 1.0f / 16384.0f, 0);
}